// round 10
// baseline (speedup 1.0000x reference)
#include <cuda_runtime.h>
#include <cuda_bf16.h>

// x viewed as [T tokens][H=32 heads][D=128 dims], fp32.
// For each (t, d): 32-point Walsh-Hadamard across h, * 1/sqrt(32).
// Persistent grid-stride version: fixed grid ~ SMs * resident blocks,
// each thread loops over (t, d) columns. Removes wave-transition
// overhead of the 8192-CTA launch and smooths the CTA-tail spread
// caused by the 32-deep front-batched LDG burst per column.

#define NUM_HEADS 32
#define HEAD_DIM  128
#define NBLOCKS   912   // ~152 SMs * 6 resident CTAs (40 regs, 256 thr)

__global__ __launch_bounds__(256) void had32_kernel_v4(
    const float* __restrict__ x, float* __restrict__ out, long n_cols)
{
    const long stride = (long)gridDim.x * blockDim.x;

    for (long col = (long)blockIdx.x * blockDim.x + threadIdx.x;
         col < n_cols; col += stride) {

        long t = col >> 7;          // col / 128
        int  d = (int)(col & 127);  // col % 128

        const float* __restrict__ in_base  = x   + (t << 12) + d;  // t*4096 + d
        float*       __restrict__ out_base = out + (t << 12) + d;

        float v[NUM_HEADS];
        #pragma unroll
        for (int h = 0; h < NUM_HEADS; ++h)
            v[h] = __ldcs(in_base + (h << 7));   // 128B/warp, coalesced

        // In-place fast WHT, Sylvester ordering (matches reference).
        #pragma unroll
        for (int len = 1; len < NUM_HEADS; len <<= 1) {
            #pragma unroll
            for (int i = 0; i < NUM_HEADS; ++i) {
                if ((i & len) == 0) {
                    float a = v[i];
                    float b = v[i + len];
                    v[i]       = a + b;
                    v[i + len] = a - b;
                }
            }
        }

        const float scale = 0.17677669529663687f;  // 1/sqrt(32)
        #pragma unroll
        for (int h = 0; h < NUM_HEADS; ++h)
            __stcs(out_base + (h << 7), v[h] * scale);
    }
}

extern "C" void kernel_launch(void* const* d_in, const int* in_sizes, int n_in,
                              void* d_out, int out_size)
{
    const float* x = (const float*)d_in[0];
    float* out = (float*)d_out;

    long n = (long)in_sizes[0];          // total elements
    long n_cols = n / NUM_HEADS;         // one column per (token, dim)

    had32_kernel_v4<<<NBLOCKS, 256>>>(x, out, n_cols);
}